// round 1
// baseline (speedup 1.0000x reference)
#include <cuda_runtime.h>
#include <cstdint>

// Problem constants
#define BB   64      // batch
#define EE   512     // embedding dim
#define HH   1024    // hidden dim
#define VV   16000   // vocab
#define H3   3072    // 3*HH
#define TT   64      // time steps
#define SOS  1
#define PADI 0

// ---------------- device scratch (no allocations allowed) ----------------
__device__ float g_h[BB * HH];          // current hidden  [64,1024]
__device__ float g_x[BB * EE];          // current embedded input [64,512]
__device__ float g_gx[BB * H3];         // x @ w_ih^T + b_ih
__device__ float g_gh1[BB * H3];        // h @ w_hh^T (k 0..511)
__device__ float g_gh2[BB * H3];        // h @ w_hh^T (k 512..1023)
__device__ float g_logits[BB * VV];     // per-step logits

// ---------------- packed f32x2 helpers ----------------
__device__ __forceinline__ unsigned long long pack_dup(float a) {
    unsigned long long r;
    unsigned int ai = __float_as_uint(a);
    asm("mov.b64 %0, {%1, %1};" : "=l"(r) : "r"(ai));
    return r;
}
__device__ __forceinline__ void ffma2(unsigned long long& acc,
                                      unsigned long long a2,
                                      unsigned long long b2) {
    asm("fma.rn.f32x2 %0, %1, %2, %0;" : "+l"(acc) : "l"(a2), "l"(b2));
}

// ---------------- 64xN GEMM tile body ----------------
// C[m, jbase+n] (m=0..63 batch rows, n=0..63 tile cols)
//   = sum_{k=kbase}^{kbase+KTILES*32-1} A[m, k] * W[jbase+n, k]  (+ bias)
// 256 threads, per-thread 4x4 microtile, packed f32x2 accumulators.
template <int KTILES>
__device__ __forceinline__ void gemm64_body(
    const float* __restrict__ A, int lda,
    const float* __restrict__ W, int ldw,
    int kbase,
    float* __restrict__ C, int ldc,
    const float* __restrict__ bias, int jbase,
    float (*As)[66], float (*Ws)[66])
{
    const int t  = threadIdx.x;
    const int tx = t & 15;          // n direction
    const int ty = t >> 4;          // m direction
    const int m0 = ty * 4;
    const int n0 = tx * 4;

    unsigned long long acc[4][2];
#pragma unroll
    for (int i = 0; i < 4; i++) { acc[i][0] = 0ull; acc[i][1] = 0ull; }

#pragma unroll 1
    for (int kt = 0; kt < KTILES; kt++) {
        const int k0 = kbase + kt * 32;
        // load 64x32 A tile and 64x32 W tile, transposed into [kk][m]
#pragma unroll
        for (int i = 0; i < 8; i++) {
            int idx = t + i * 256;
            int kk = idx & 31;
            int m  = idx >> 5;
            As[kk][m] = A[m * lda + k0 + kk];
            Ws[kk][m] = W[(jbase + m) * ldw + k0 + kk];
        }
        __syncthreads();
#pragma unroll
        for (int kk = 0; kk < 32; kk++) {
            unsigned long long b0 = *(const unsigned long long*)&Ws[kk][n0];
            unsigned long long b1 = *(const unsigned long long*)&Ws[kk][n0 + 2];
#pragma unroll
            for (int mi = 0; mi < 4; mi++) {
                unsigned long long a2 = pack_dup(As[kk][m0 + mi]);
                ffma2(acc[mi][0], a2, b0);
                ffma2(acc[mi][1], a2, b1);
            }
        }
        __syncthreads();
    }

    // epilogue
#pragma unroll
    for (int mi = 0; mi < 4; mi++) {
        int m = m0 + mi;
        int j = jbase + n0;
        float4 v;
        v.x = __uint_as_float((unsigned int)(acc[mi][0]));
        v.y = __uint_as_float((unsigned int)(acc[mi][0] >> 32));
        v.z = __uint_as_float((unsigned int)(acc[mi][1]));
        v.w = __uint_as_float((unsigned int)(acc[mi][1] >> 32));
        if (bias) {
            v.x += bias[j];
            v.y += bias[j + 1];
            v.z += bias[j + 2];
            v.w += bias[j + 3];
        }
        *(float4*)&C[(size_t)m * ldc + j] = v;
    }
}

// ---------------- K1: GRU gate GEMMs (144 blocks of equal K=512 work) ----------------
__global__ void __launch_bounds__(256)
gru_gates_kernel(const float* __restrict__ w_ih,
                 const float* __restrict__ w_hh,
                 const float* __restrict__ b_ih)
{
    __shared__ float As[32][66];
    __shared__ float Ws[32][66];
    int bx = blockIdx.x;
    if (bx < 48) {
        // gx = x @ w_ih^T + b_ih
        gemm64_body<16>(g_x, EE, w_ih, EE, 0, g_gx, H3, b_ih, bx * 64, As, Ws);
    } else if (bx < 96) {
        // gh (k 0..511)
        gemm64_body<16>(g_h, HH, w_hh, HH, 0, g_gh1, H3, nullptr, (bx - 48) * 64, As, Ws);
    } else {
        // gh (k 512..1023)
        gemm64_body<16>(g_h, HH, w_hh, HH, 512, g_gh2, H3, nullptr, (bx - 96) * 64, As, Ws);
    }
}

// ---------------- K2: GRU combine ----------------
__global__ void __launch_bounds__(256)
gru_combine_kernel(const float* __restrict__ b_hh)
{
    int i = blockIdx.x * 256 + threadIdx.x;   // 65536 = 64*1024
    int b  = i >> 10;
    int ii = i & 1023;
    const float* gx = g_gx + (size_t)b * H3;
    float ghr = g_gh1[(size_t)b * H3 + ii]        + g_gh2[(size_t)b * H3 + ii]        + b_hh[ii];
    float ghz = g_gh1[(size_t)b * H3 + HH + ii]   + g_gh2[(size_t)b * H3 + HH + ii]   + b_hh[HH + ii];
    float ghn = g_gh1[(size_t)b * H3 + 2*HH + ii] + g_gh2[(size_t)b * H3 + 2*HH + ii] + b_hh[2*HH + ii];
    float r = 1.0f / (1.0f + expf(-(gx[ii] + ghr)));
    float z = 1.0f / (1.0f + expf(-(gx[HH + ii] + ghz)));
    float n = tanhf(gx[2*HH + ii] + r * ghn);
    float h = g_h[i];
    g_h[i] = (1.0f - z) * n + z * h;
}

// ---------------- K3: fc logits GEMM (250 blocks) ----------------
__global__ void __launch_bounds__(256)
fc_gemm_kernel(const float* __restrict__ fc_w,
               const float* __restrict__ fc_b)
{
    __shared__ float As[32][66];
    __shared__ float Ws[32][66];
    gemm64_body<32>(g_h, HH, fc_w, HH, 0, g_logits, VV, fc_b, blockIdx.x * 64, As, Ws);
}

// ---------------- K4: log_softmax + argmax + embedding gather ----------------
__global__ void __launch_bounds__(256)
softmax_argmax_kernel(const float* __restrict__ emb,
                      float* __restrict__ out, int t)
{
    int b   = blockIdx.x;
    int tid = threadIdx.x;
    const float* lg = g_logits + (size_t)b * VV;
    __shared__ float sval[256];
    __shared__ int   sidx[256];

    // pass 1: max + argmax (first-occurrence tie-break, like jnp.argmax)
    float vmax = -3.4e38f;
    int   amax = VV;
    for (int j = tid; j < VV; j += 256) {
        float v = lg[j];
        if (v > vmax) { vmax = v; amax = j; }
    }
    sval[tid] = vmax; sidx[tid] = amax;
    __syncthreads();
    for (int s = 128; s > 0; s >>= 1) {
        if (tid < s) {
            float v2 = sval[tid + s]; int i2 = sidx[tid + s];
            if (v2 > sval[tid] || (v2 == sval[tid] && i2 < sidx[tid])) {
                sval[tid] = v2; sidx[tid] = i2;
            }
        }
        __syncthreads();
    }
    float gmax = sval[0];
    int   tok  = sidx[0];
    __syncthreads();

    // pass 2: sum(exp(l - max))
    float s = 0.0f;
    for (int j = tid; j < VV; j += 256) s += expf(lg[j] - gmax);
    sval[tid] = s;
    __syncthreads();
    for (int r = 128; r > 0; r >>= 1) {
        if (tid < r) sval[tid] += sval[tid + r];
        __syncthreads();
    }
    float lse = gmax + logf(sval[0]);

    // pass 3: write log-probs
    float* o = out + ((size_t)b * TT + t) * (size_t)VV;
    for (int j = tid; j < VV; j += 256) o[j] = lg[j] - lse;

    // pass 4: gather next-step embedding (padding_idx row forced to zero)
    for (int k = tid; k < EE; k += 256) {
        g_x[b * EE + k] = (tok == PADI) ? 0.0f : emb[(size_t)tok * EE + k];
    }
}

// ---------------- init / finalize ----------------
__global__ void __launch_bounds__(256)
init_kernel(const float* __restrict__ enc, const float* __restrict__ emb)
{
    int i = blockIdx.x * 256 + threadIdx.x;   // 65536
    g_h[i] = enc[i];                           // encoder_hidden[0] flat [64*1024]
    if (i < BB * EE) {
        int k = i & (EE - 1);
        g_x[i] = emb[SOS * EE + k];            // SOS row (SOS != PAD)
    }
}

__global__ void __launch_bounds__(256)
finalize_kernel(float* __restrict__ out)
{
    int i = blockIdx.x * 256 + threadIdx.x;   // 65536
    out[(size_t)BB * TT * VV + i] = g_h[i];
}

// ---------------- launch ----------------
extern "C" void kernel_launch(void* const* d_in, const int* in_sizes, int n_in,
                              void* d_out, int out_size)
{
    // inputs: 0 target(i64, unused), 1 encoder_hidden, 2 emb, 3 w_ih, 4 w_hh,
    //         5 b_ih, 6 b_hh, 7 fc_w, 8 fc_b
    const float* enc  = (const float*)d_in[1];
    const float* emb  = (const float*)d_in[2];
    const float* w_ih = (const float*)d_in[3];
    const float* w_hh = (const float*)d_in[4];
    const float* b_ih = (const float*)d_in[5];
    const float* b_hh = (const float*)d_in[6];
    const float* fc_w = (const float*)d_in[7];
    const float* fc_b = (const float*)d_in[8];
    float* out = (float*)d_out;

    init_kernel<<<256, 256>>>(enc, emb);
    for (int t = 0; t < TT; t++) {
        gru_gates_kernel<<<144, 256>>>(w_ih, w_hh, b_ih);
        gru_combine_kernel<<<256, 256>>>(b_hh);
        fc_gemm_kernel<<<250, 256>>>(fc_w, fc_b);
        softmax_argmax_kernel<<<BB, 256>>>(emb, out, t);
    }
    finalize_kernel<<<256, 256>>>(out);
}

// round 2
// speedup vs baseline: 1.3346x; 1.3346x over previous
#include <cuda_runtime.h>
#include <cstdint>

// Problem constants
#define BB   64      // batch
#define EE   512     // embedding dim
#define HH   1024    // hidden dim
#define VV   16000   // vocab
#define H3   3072    // 3*HH
#define TT   64      // time steps
#define SOS  1
#define PADI 0

typedef unsigned long long ull;
struct __align__(16) U2 { ull x, y; };

// ---------------- device scratch (no runtime allocations allowed) ----------------
__device__ float g_h[BB * HH];            // hidden, row-major [b][k]
__device__ float g_hT[HH * BB];           // hidden, K-major [k][b]
__device__ float g_xT[EE * BB];           // embedded input, K-major [k][b]
__device__ float g_gx[BB * H3];           // x @ w_ih^T + b_ih
__device__ float g_gh1[BB * H3];          // h @ w_hh^T (k 0..511)
__device__ float g_gh2[BB * H3];          // h @ w_hh^T (k 512..1023)
__device__ float g_logits[BB * VV];       // per-step logits
__device__ float g_lse[BB];               // per-row logsumexp
__device__ float g_fcwT[(size_t)HH * VV]; // fc_w transposed  [1024][16000]
__device__ float g_wihT[EE * H3];         // w_ih transposed  [512][3072]
__device__ float g_whhT[HH * H3];         // w_hh transposed  [1024][3072]

// ---------------- helpers ----------------
__device__ __forceinline__ ull pack_dup(float a) {
    ull r; unsigned int ai = __float_as_uint(a);
    asm("mov.b64 %0, {%1, %1};" : "=l"(r) : "r"(ai));
    return r;
}
__device__ __forceinline__ void ffma2(ull& acc, ull a2, ull b2) {
    asm("fma.rn.f32x2 %0, %1, %2, %0;" : "+l"(acc) : "l"(a2), "l"(b2));
}
__device__ __forceinline__ void cp_async16(uint32_t saddr, const void* gptr) {
    asm volatile("cp.async.ca.shared.global [%0], [%1], 16;" :: "r"(saddr), "l"(gptr));
}
__device__ __forceinline__ void cp_commit() {
    asm volatile("cp.async.commit_group;");
}
template <int N>
__device__ __forceinline__ void cp_wait() {
    asm volatile("cp.async.wait_group %0;" :: "n"(N));
}
__device__ __forceinline__ float ulo(ull v) { return __uint_as_float((unsigned int)v); }
__device__ __forceinline__ float uhi(ull v) { return __uint_as_float((unsigned int)(v >> 32)); }

// ---------------- double-buffered K-major GEMM body ----------------
// C[m, jbase+n] += sum_k AT[k][m] * WT[k][jbase+n]  for the K-range
// [kbase, kbase + 32*KTILES). AT is [K][64] K-major, WT is [K][ldwt] K-major.
// 256 threads, microtile 4 x (BN/16), packed f32x2 accumulators, cp.async
// double-buffered smem, register-pipelined inner loop.
template <int BN, int KTILES>
__device__ __forceinline__ void gemm_db(
    const float* __restrict__ AT,
    const float* __restrict__ WT, int ldwt, int kbase,
    float* __restrict__ C, int ldc,
    const float* __restrict__ bias, int jbase,
    float* sm)
{
    constexpr int NR  = BN / 16;   // cols per thread: 8 (BN=128) or 4 (BN=64)
    constexpr int NU  = NR / 2;    // f32x2 accumulators per m-row
    constexpr int ASZ = 32 * 64;   // floats per A tile
    constexpr int WSZ = 32 * BN;   // floats per W tile
    constexpr int NF4 = BN / 4;    // float4s per W row

    const int t  = threadIdx.x;
    const int tx = t & 15;
    const int ty = t >> 4;
    const int m0 = ty * 4;
    const int n0 = tx * NR;

    const uint32_t sbase = (uint32_t)__cvta_generic_to_shared(sm);

    ull acc[4][NU];
#pragma unroll
    for (int mi = 0; mi < 4; mi++)
#pragma unroll
        for (int q = 0; q < NU; q++) acc[mi][q] = 0ull;

    // tile loader: contiguous 16B cp.async, no transposition anywhere
    auto load_tile = [&](int kt, int buf) {
        const int k0 = kbase + kt * 32;
        // A tile: 32 rows x 64 floats, fully contiguous 8KB in global
        const char* gA = (const char*)(AT + (size_t)k0 * 64);
        const uint32_t sA = sbase + buf * (ASZ * 4);
#pragma unroll
        for (int j = 0; j < 2; j++) {               // 512 chunks / 256 thr
            int idx = t + j * 256;
            cp_async16(sA + idx * 16, gA + idx * 16);
        }
        // W tile: 32 rows x BN floats, each row contiguous
        const uint32_t sW = sbase + (2 * ASZ + buf * WSZ) * 4;
#pragma unroll
        for (int j = 0; j < (32 * NF4) / 256; j++) {
            int idx = t + j * 256;
            int row = idx / NF4;
            int c4  = idx - row * NF4;
            const float* g = WT + (size_t)(k0 + row) * ldwt + jbase + c4 * 4;
            cp_async16(sW + (row * BN + c4 * 4) * 4, (const void*)g);
        }
        cp_commit();
    };

    load_tile(0, 0);

#pragma unroll 1
    for (int kt = 0; kt < KTILES; kt++) {
        const int buf = kt & 1;
        if (kt + 1 < KTILES) { load_tile(kt + 1, buf ^ 1); cp_wait<1>(); }
        else                 { cp_wait<0>(); }
        __syncthreads();

        const float* As = sm + buf * ASZ;             // [32][64]
        const float* Ws = sm + 2 * ASZ + buf * WSZ;   // [32][BN]

        ull ar[2][4];
        ull br[2][NU];
        // stage kk = 0
        {
            const float* w = Ws + n0;
#pragma unroll
            for (int q = 0; q < NR / 4; q++) {
                U2 u = *(const U2*)(w + q * 4);
                br[0][2 * q] = u.x; br[0][2 * q + 1] = u.y;
            }
#pragma unroll
            for (int mi = 0; mi < 4; mi++) ar[0][mi] = pack_dup(As[m0 + mi]);
        }
#pragma unroll
        for (int kk = 0; kk < 32; kk++) {
            const int cur = kk & 1, nx = cur ^ 1;
            if (kk < 31) {
                const float* w = Ws + (kk + 1) * BN + n0;
#pragma unroll
                for (int q = 0; q < NR / 4; q++) {
                    U2 u = *(const U2*)(w + q * 4);
                    br[nx][2 * q] = u.x; br[nx][2 * q + 1] = u.y;
                }
                const float* a = As + (kk + 1) * 64 + m0;
#pragma unroll
                for (int mi = 0; mi < 4; mi++) ar[nx][mi] = pack_dup(a[mi]);
            }
#pragma unroll
            for (int mi = 0; mi < 4; mi++)
#pragma unroll
                for (int q = 0; q < NU; q++)
                    ffma2(acc[mi][q], ar[cur][mi], br[cur][q]);
        }
        __syncthreads();
    }

    // epilogue
#pragma unroll
    for (int mi = 0; mi < 4; mi++) {
        const int m = m0 + mi;
        const int j = jbase + n0;
#pragma unroll
        for (int q = 0; q < NR / 4; q++) {
            float4 v;
            v.x = ulo(acc[mi][2 * q]);     v.y = uhi(acc[mi][2 * q]);
            v.z = ulo(acc[mi][2 * q + 1]); v.w = uhi(acc[mi][2 * q + 1]);
            if (bias) {
                v.x += bias[j + q * 4 + 0];
                v.y += bias[j + q * 4 + 1];
                v.z += bias[j + q * 4 + 2];
                v.w += bias[j + q * 4 + 3];
            }
            *(float4*)&C[(size_t)m * ldc + j + q * 4] = v;
        }
    }
}

// ---------------- weight transpose (runs once per launch) ----------------
// src [R][C] -> dst [C][R]
__global__ void __launch_bounds__(256)
transpose_kernel(const float* __restrict__ src, float* __restrict__ dst,
                 int R, int C)
{
    __shared__ float tile[32][33];
    const int c0 = blockIdx.x * 32, r0 = blockIdx.y * 32;
    const int tx = threadIdx.x & 31, ty = threadIdx.x >> 5;   // (32,8)
#pragma unroll
    for (int i = 0; i < 32; i += 8)
        tile[ty + i][tx] = src[(size_t)(r0 + ty + i) * C + c0 + tx];
    __syncthreads();
#pragma unroll
    for (int i = 0; i < 32; i += 8)
        dst[(size_t)(c0 + ty + i) * R + r0 + tx] = tile[tx][ty + i];
}

// ---------------- K1: GRU gate GEMMs (144 equal blocks) ----------------
__global__ void __launch_bounds__(256)
gru_gates_kernel(const float* __restrict__ b_ih)
{
    __shared__ float sm[2 * (32 * 64 + 32 * 64)];   // 32KB
    const int bx = blockIdx.x;
    if (bx < 48) {
        gemm_db<64, 16>(g_xT, g_wihT, H3, 0,   g_gx,  H3, b_ih,    bx * 64, sm);
    } else if (bx < 96) {
        gemm_db<64, 16>(g_hT, g_whhT, H3, 0,   g_gh1, H3, nullptr, (bx - 48) * 64, sm);
    } else {
        gemm_db<64, 16>(g_hT, g_whhT, H3, 512, g_gh2, H3, nullptr, (bx - 96) * 64, sm);
    }
}

// ---------------- K2: GRU combine (writes h and hT) ----------------
__global__ void __launch_bounds__(256)
gru_combine_kernel(const float* __restrict__ b_hh)
{
    const int i  = blockIdx.x * 256 + threadIdx.x;   // 65536
    const int b  = i >> 10;
    const int ii = i & 1023;
    const float* gx = g_gx + (size_t)b * H3;
    float ghr = g_gh1[(size_t)b * H3 + ii]          + g_gh2[(size_t)b * H3 + ii]          + b_hh[ii];
    float ghz = g_gh1[(size_t)b * H3 + HH + ii]     + g_gh2[(size_t)b * H3 + HH + ii]     + b_hh[HH + ii];
    float ghn = g_gh1[(size_t)b * H3 + 2 * HH + ii] + g_gh2[(size_t)b * H3 + 2 * HH + ii] + b_hh[2 * HH + ii];
    float r = 1.0f / (1.0f + expf(-(gx[ii] + ghr)));
    float z = 1.0f / (1.0f + expf(-(gx[HH + ii] + ghz)));
    float n = tanhf(gx[2 * HH + ii] + r * ghn);
    float h = g_h[i];
    float hn = (1.0f - z) * n + z * h;
    g_h[i] = hn;
    g_hT[ii * BB + b] = hn;
}

// ---------------- K3: fc logits GEMM (125 blocks, single wave) ----------------
__global__ void __launch_bounds__(256)
fc_gemm_kernel(const float* __restrict__ fc_b)
{
    __shared__ float sm[2 * (32 * 64 + 32 * 128)];  // 48KB
    gemm_db<128, 32>(g_hT, g_fcwT, VV, 0, g_logits, VV, fc_b, blockIdx.x * 128, sm);
}

// ---------------- K4a: row stats (max/argmax/lse) + embedding gather ----------------
__global__ void __launch_bounds__(512)
stats_kernel(const float* __restrict__ emb)
{
    const int b   = blockIdx.x;
    const int tid = threadIdx.x;
    const float* lg = g_logits + (size_t)b * VV;
    __shared__ float sval[512];
    __shared__ int   sidx[512];

    // max + argmax (first-occurrence tie-break, like jnp.argmax)
    float vmax = -3.4e38f;
    int   amax = VV;
    for (int j = tid; j < VV; j += 512) {
        float v = lg[j];
        if (v > vmax) { vmax = v; amax = j; }
    }
    sval[tid] = vmax; sidx[tid] = amax;
    __syncthreads();
    for (int s = 256; s > 0; s >>= 1) {
        if (tid < s) {
            float v2 = sval[tid + s]; int i2 = sidx[tid + s];
            if (v2 > sval[tid] || (v2 == sval[tid] && i2 < sidx[tid])) {
                sval[tid] = v2; sidx[tid] = i2;
            }
        }
        __syncthreads();
    }
    const float gmax = sval[0];
    const int   tok  = sidx[0];
    __syncthreads();

    // sum(exp(l - max))
    float s = 0.0f;
    for (int j = tid; j < VV; j += 512) s += expf(lg[j] - gmax);
    sval[tid] = s;
    __syncthreads();
    for (int r = 256; r > 0; r >>= 1) {
        if (tid < r) sval[tid] += sval[tid + r];
        __syncthreads();
    }
    if (tid == 0) g_lse[b] = gmax + logf(sval[0]);

    // next-step embedding, K-major (padding_idx row forced to zero)
    for (int k = tid; k < EE; k += 512) {
        g_xT[k * BB + b] = (tok == PADI) ? 0.0f : emb[(size_t)tok * EE + k];
    }
}

// ---------------- K4b: streaming log-prob write ----------------
__global__ void __launch_bounds__(256)
logp_write_kernel(float* __restrict__ out, int t)
{
    const int idx = blockIdx.x * 256 + threadIdx.x;  // float4 id, 256000 total
    const int b   = idx / 4000;
    const int j4  = idx - b * 4000;
    float4 v = ((const float4*)(g_logits + (size_t)b * VV))[j4];
    const float lse = g_lse[b];
    v.x -= lse; v.y -= lse; v.z -= lse; v.w -= lse;
    ((float4*)(out + ((size_t)b * TT + t) * VV))[j4] = v;
}

// ---------------- init / finalize ----------------
__global__ void __launch_bounds__(256)
init_kernel(const float* __restrict__ enc, const float* __restrict__ emb)
{
    const int i = blockIdx.x * 256 + threadIdx.x;    // 65536
    float h = enc[i];
    g_h[i] = h;
    g_hT[(i & 1023) * BB + (i >> 10)] = h;
    if (i < EE * BB) {                               // g_xT[k][b] = emb[SOS][k]
        g_xT[i] = emb[SOS * EE + (i >> 6)];
    }
}

__global__ void __launch_bounds__(256)
finalize_kernel(float* __restrict__ out)
{
    const int i = blockIdx.x * 256 + threadIdx.x;    // 65536
    out[(size_t)BB * TT * VV + i] = g_h[i];
}

// ---------------- launch ----------------
extern "C" void kernel_launch(void* const* d_in, const int* in_sizes, int n_in,
                              void* d_out, int out_size)
{
    // inputs: 0 target(i64, unused), 1 encoder_hidden, 2 emb, 3 w_ih, 4 w_hh,
    //         5 b_ih, 6 b_hh, 7 fc_w, 8 fc_b
    const float* enc  = (const float*)d_in[1];
    const float* emb  = (const float*)d_in[2];
    const float* w_ih = (const float*)d_in[3];
    const float* w_hh = (const float*)d_in[4];
    const float* b_ih = (const float*)d_in[5];
    const float* b_hh = (const float*)d_in[6];
    const float* fc_w = (const float*)d_in[7];
    const float* fc_b = (const float*)d_in[8];
    float* out = (float*)d_out;

    // one-time per-launch weight transposes into K-major layout
    {
        float* fcwT = nullptr; cudaGetSymbolAddress((void**)&fcwT, g_fcwT);
        float* wihT = nullptr; cudaGetSymbolAddress((void**)&wihT, g_wihT);
        float* whhT = nullptr; cudaGetSymbolAddress((void**)&whhT, g_whhT);
        transpose_kernel<<<dim3(HH / 32, VV / 32), 256>>>(fc_w, fcwT, VV, HH);
        transpose_kernel<<<dim3(EE / 32, H3 / 32), 256>>>(w_ih, wihT, H3, EE);
        transpose_kernel<<<dim3(HH / 32, H3 / 32), 256>>>(w_hh, whhT, H3, HH);
    }

    init_kernel<<<256, 256>>>(enc, emb);
    for (int t = 0; t < TT; t++) {
        gru_gates_kernel<<<144, 256>>>(b_ih);
        gru_combine_kernel<<<256, 256>>>(b_hh);
        fc_gemm_kernel<<<125, 256>>>(fc_b);
        stats_kernel<<<BB, 512>>>(emb);
        logp_write_kernel<<<1000, 256>>>(out, t);
    }
    finalize_kernel<<<256, 256>>>(out);
}